// round 1
// baseline (speedup 1.0000x reference)
#include <cuda_runtime.h>
#include <cstdint>

// Problem constants (fixed by the dataset)
#define NN 50000
#define EE 800000
#define FF 64
#define HH 128
#define CAP 96   // ELL capacity per row; deg ~ Poisson(16), P(deg>96) ~ 0

// ---------------- scratch (static device globals; no allocations) -----------
__device__ int   g_cnt[NN];
__device__ float g_dinv[NN];
__device__ int2  g_ell[(size_t)NN * CAP];          // (.x = col, .y = ew bits)
__device__ float g_T1[(size_t)NN * FF];
__device__ float g_T2[(size_t)NN * FF];
__device__ float g_T3[(size_t)NN * FF];

// ---------------- small helpers: packed f32x2 math --------------------------
__device__ __forceinline__ unsigned long long pk2(float a, float b) {
    unsigned long long r;
    asm("mov.b64 %0, {%1, %2};" : "=l"(r) : "f"(a), "f"(b));
    return r;
}
__device__ __forceinline__ void fma2(unsigned long long& d,
                                     unsigned long long a, unsigned long long b) {
    asm("fma.rn.f32x2 %0, %1, %2, %0;" : "+l"(d) : "l"(a), "l"(b));
}
__device__ __forceinline__ void upk2(unsigned long long v, float& lo, float& hi) {
    asm("mov.b64 {%0, %1}, %2;" : "=f"(lo), "=f"(hi) : "l"(v));
}

// ---------------- graph build ------------------------------------------------
__global__ void k_zero_cnt() {
    int i = blockIdx.x * blockDim.x + threadIdx.x;
    if (i < NN) g_cnt[i] = 0;
}

__global__ void k_fill(const int* __restrict__ ei) {
    int e = blockIdx.x * blockDim.x + threadIdx.x;
    if (e >= EE) return;
    int r = ei[e];
    int c = ei[EE + e];
    int s = atomicAdd(&g_cnt[r], 1);
    if (s < CAP) g_ell[(size_t)r * CAP + s].x = c;
}

__global__ void k_dinv() {
    int i = blockIdx.x * blockDim.x + threadIdx.x;
    if (i >= NN) return;
    int d = g_cnt[i];
    g_dinv[i] = (d > 0) ? rsqrtf((float)d) : 0.0f;
}

__global__ void k_ew() {
    int idx = blockIdx.x * blockDim.x + threadIdx.x;
    if (idx >= NN * CAP) return;
    int r = idx / CAP;
    int s = idx - r * CAP;
    int cnt = g_cnt[r]; if (cnt > CAP) cnt = CAP;
    if (s >= cnt) return;
    int c = g_ell[idx].x;
    g_ell[idx].y = __float_as_int(-g_dinv[r] * g_dinv[c]);
}

// ---------------- SPMM: warp per row, atomic-free gather ---------------------
// PHASE 1: T1 = L*X          (src = x,     prev = -)
// PHASE 2: T2 = 2*L*T1 - X   (src = g_T1,  prev = x)
// PHASE 3: T3 = 2*L*T2 - T1  (src = g_T2,  prev = g_T1)
template <int PHASE>
__global__ void k_spmm(const float* __restrict__ x) {
    int row  = (blockIdx.x * blockDim.x + threadIdx.x) >> 5;
    int lane = threadIdx.x & 31;
    if (row >= NN) return;
    int l2 = lane * 2;

    const float* __restrict__ src  = (PHASE == 1) ? x
                                   : (PHASE == 2) ? g_T1 : g_T2;
    const float* __restrict__ prev = (PHASE == 2) ? x
                                   : (PHASE == 3) ? g_T1 : nullptr;
    float* __restrict__ dst = (PHASE == 1) ? g_T1
                            : (PHASE == 2) ? g_T2 : g_T3;

    int cnt = g_cnt[row]; if (cnt > CAP) cnt = CAP;
    const int2* ep = g_ell + (size_t)row * CAP;

    float ax = 0.f, ay = 0.f;
    int i = 0;
    int n4 = cnt & ~3;
    for (; i < n4; i += 4) {
        int4 ea = *(const int4*)(ep + i);       // {col0, ew0, col1, ew1}
        int4 eb = *(const int4*)(ep + i + 2);
        float2 v0 = *(const float2*)(src + (size_t)ea.x * FF + l2);
        float2 v1 = *(const float2*)(src + (size_t)ea.z * FF + l2);
        float2 v2 = *(const float2*)(src + (size_t)eb.x * FF + l2);
        float2 v3 = *(const float2*)(src + (size_t)eb.z * FF + l2);
        float w0 = __int_as_float(ea.y), w1 = __int_as_float(ea.w);
        float w2 = __int_as_float(eb.y), w3 = __int_as_float(eb.w);
        ax = fmaf(w0, v0.x, ax); ay = fmaf(w0, v0.y, ay);
        ax = fmaf(w1, v1.x, ax); ay = fmaf(w1, v1.y, ay);
        ax = fmaf(w2, v2.x, ax); ay = fmaf(w2, v2.y, ay);
        ax = fmaf(w3, v3.x, ax); ay = fmaf(w3, v3.y, ay);
    }
    for (; i < cnt; i++) {
        int2 e = ep[i];
        float2 v = *(const float2*)(src + (size_t)e.x * FF + l2);
        float w = __int_as_float(e.y);
        ax = fmaf(w, v.x, ax); ay = fmaf(w, v.y, ay);
    }

    float2 res;
    if (PHASE >= 2) {
        float2 p = *(const float2*)(prev + (size_t)row * FF + l2);
        res.x = fmaf(2.f, ax, -p.x);
        res.y = fmaf(2.f, ay, -p.y);
    } else {
        res.x = ax; res.y = ay;
    }
    *(float2*)(dst + (size_t)row * FF + l2) = res;
}

// ---------------- fused GEMM + bias + tanh + final dot -----------------------
// out[n,h] = sum_k T_k[n,:]@W_k[:,h] + b[h];  y[n] = sum_h tanh(out)*fw[h] + fb
// Tile: 128 rows x 128 cols (all of H), K=256 in 8 chunks of 32.
// 256 threads, 8x8 micro-tile per thread, packed f32x2 FMAs.
__global__ __launch_bounds__(256, 2)
void k_gemm(const float* __restrict__ X, const float* __restrict__ W,
            const float* __restrict__ bias, const float* __restrict__ fw,
            const float* __restrict__ fb, float* __restrict__ y) {
    __shared__ float As[128][36];   // [row][kk], pad 36 keeps 16B stores + no conflicts
    __shared__ float Bs[32][128];   // [kk][h]

    int tid = threadIdx.x;
    int tx = tid & 15, ty = tid >> 4;
    int rowBase = blockIdx.x * 128;

    unsigned long long acc[8][4];
#pragma unroll
    for (int i = 0; i < 8; i++)
#pragma unroll
        for (int j = 0; j < 4; j++) acc[i][j] = 0ull;

    const float* srcs[4] = {X, g_T1, g_T2, g_T3};

    for (int ch = 0; ch < 8; ch++) {
        const float* A  = srcs[ch >> 1];
        int kofs        = (ch & 1) * 32;
        const float* Bp = W + (ch >> 1) * (FF * HH) + kofs * HH;

#pragma unroll
        for (int t = 0; t < 4; t++) {
            int g = t * 256 + tid;          // 0..1023 float4s
            int r = g >> 3, c4 = g & 7;     // 8 float4 per 32-wide row
            int grow = rowBase + r;
            float4 v = make_float4(0.f, 0.f, 0.f, 0.f);
            if (grow < NN)
                v = *(const float4*)(A + (size_t)grow * FF + kofs + c4 * 4);
            *(float4*)&As[r][c4 * 4] = v;
            ((float4*)Bs)[g] = ((const float4*)Bp)[g];
        }
        __syncthreads();

#pragma unroll 8
        for (int kk = 0; kk < 32; kk++) {
            float4 b0 = *(const float4*)&Bs[kk][tx * 8];
            float4 b1 = *(const float4*)&Bs[kk][tx * 8 + 4];
            unsigned long long w0 = pk2(b0.x, b0.y), w1 = pk2(b0.z, b0.w);
            unsigned long long w2 = pk2(b1.x, b1.y), w3 = pk2(b1.z, b1.w);
#pragma unroll
            for (int i = 0; i < 8; i++) {
                float a = As[ty * 8 + i][kk];
                unsigned long long a2 = pk2(a, a);
                fma2(acc[i][0], a2, w0);
                fma2(acc[i][1], a2, w1);
                fma2(acc[i][2], a2, w2);
                fma2(acc[i][3], a2, w3);
            }
        }
        __syncthreads();
    }

    // epilogue: bias + tanh + dot with fw, reduce over the 16 tx lanes
    float bia[8], fwv[8];
#pragma unroll
    for (int j = 0; j < 8; j++) {
        bia[j] = bias[tx * 8 + j];
        fwv[j] = fw[tx * 8 + j];
    }
    float fbv = fb[0];

    float part[8];
#pragma unroll
    for (int i = 0; i < 8; i++) {
        float p = 0.f;
#pragma unroll
        for (int jj = 0; jj < 4; jj++) {
            float lo, hi;
            upk2(acc[i][jj], lo, hi);
            p += tanhf(lo + bia[jj * 2])     * fwv[jj * 2];
            p += tanhf(hi + bia[jj * 2 + 1]) * fwv[jj * 2 + 1];
        }
        part[i] = p;
    }
    // warp = 2 ty-groups x 16 tx lanes; xor-reduce within each 16-lane half
#pragma unroll
    for (int ofs = 8; ofs > 0; ofs >>= 1)
#pragma unroll
        for (int i = 0; i < 8; i++)
            part[i] += __shfl_xor_sync(0xffffffffu, part[i], ofs);

    if (tx == 0) {
#pragma unroll
        for (int i = 0; i < 8; i++) {
            int r = rowBase + ty * 8 + i;
            if (r < NN) y[r] = part[i] + fbv;
        }
    }
}

// ---------------- launch -----------------------------------------------------
extern "C" void kernel_launch(void* const* d_in, const int* in_sizes, int n_in,
                              void* d_out, int out_size) {
    const float* features = (const float*)d_in[0];
    const int*   ei       = (const int*)d_in[1];
    const float* cheb_w   = (const float*)d_in[2];
    const float* cheb_b   = (const float*)d_in[3];
    const float* final_w  = (const float*)d_in[4];
    const float* final_b  = (const float*)d_in[5];
    float* y = (float*)d_out;

    k_zero_cnt<<<(NN + 255) / 256, 256>>>();
    k_fill<<<(EE + 255) / 256, 256>>>(ei);
    k_dinv<<<(NN + 255) / 256, 256>>>();
    k_ew<<<(NN * CAP + 255) / 256, 256>>>();

    int spmm_blocks = (NN + 7) / 8;          // 8 warp-rows per 256-thread block
    k_spmm<1><<<spmm_blocks, 256>>>(features);
    k_spmm<2><<<spmm_blocks, 256>>>(features);
    k_spmm<3><<<spmm_blocks, 256>>>(features);

    int gemm_blocks = (NN + 127) / 128;
    k_gemm<<<gemm_blocks, 256>>>(features, cheb_w, cheb_b, final_w, final_b, y);
}